// round 1
// baseline (speedup 1.0000x reference)
#include <cuda_runtime.h>

#define NB 1024
#define NV 64
#define NI 256
#define NO 256
constexpr float EPS = 1e-5f;

// Scratch (device globals: allowed; no runtime allocation)
__device__ float g_h[(size_t)NB * NV * NO];   // 64 MB intermediate h = feat@W + b
__device__ float g_sum[NV * NO];
__device__ float g_sqs[NV * NO];
__device__ float g_s[NV * NO];
__device__ float g_t[NV * NO];
__device__ float g_c[NV * NO];

// ---------------------------------------------------------------------------
// Kernel 0: zero the stats accumulators (must be re-zeroed every replay)
// ---------------------------------------------------------------------------
__global__ void zero_stats() {
    int i = blockIdx.x * blockDim.x + threadIdx.x;
    if (i < NV * NO) { g_sum[i] = 0.f; g_sqs[i] = 0.f; }
}

// ---------------------------------------------------------------------------
// Kernel 1: per-vertex GEMM  h[b,v,o] = sum_i feat[b,v,i]*W[v,i,o] + bias[v,o]
// plus per-(v,o) column sum / sumsq accumulation for BatchNorm stats.
// grid: (NO/128, NB/128, NV), block 256, tile 128x128x16, 8x8 microtile
// ---------------------------------------------------------------------------
__global__ __launch_bounds__(256) void gemm_stats(const float* __restrict__ feat,
                                                  const float* __restrict__ W,
                                                  const float* __restrict__ bias) {
    const int v  = blockIdx.z;
    const int n0 = blockIdx.x * 128;
    const int m0 = blockIdx.y * 128;

    __shared__ float As[16][129];   // [k][m], pad 129 -> conflict-free scalar access
    __shared__ float Bs[16][128];   // [k][n]
    __shared__ float red[16][128];  // stats reduction

    const int t  = threadIdx.x;
    const int tx = t & 15;          // n direction (8 cols each)
    const int ty = t >> 4;          // m direction (8 rows each)

    float acc[8][8];
#pragma unroll
    for (int i = 0; i < 8; i++)
#pragma unroll
        for (int j = 0; j < 8; j++) acc[i][j] = 0.f;

    const float* A  = feat + (size_t)v * NI;            // A[m][k] row stride NV*NI
    const float* Bm = W + (size_t)v * NI * NO;          // B[k][n] row stride NO

    for (int k0 = 0; k0 < NI; k0 += 16) {
        // Load A tile 128x16 -> As[k][m] (transposed)
#pragma unroll
        for (int r = 0; r < 2; r++) {
            int idx = t + r * 256;              // 0..511 float4s
            int m   = idx >> 2;                 // 0..127
            int k4  = (idx & 3) * 4;
            float4 av = *(const float4*)(A + (size_t)(m0 + m) * (NV * NI) + k0 + k4);
            As[k4 + 0][m] = av.x;
            As[k4 + 1][m] = av.y;
            As[k4 + 2][m] = av.z;
            As[k4 + 3][m] = av.w;
        }
        // Load B tile 16x128 -> Bs[k][n]
#pragma unroll
        for (int r = 0; r < 2; r++) {
            int idx = t + r * 256;
            int k   = idx >> 5;                 // 0..15
            int n4  = (idx & 31) * 4;
            *(float4*)&Bs[k][n4] =
                *(const float4*)(Bm + (size_t)(k0 + k) * NO + n0 + n4);
        }
        __syncthreads();

#pragma unroll
        for (int k = 0; k < 16; k++) {
            float a[8], bb[8];
#pragma unroll
            for (int i = 0; i < 8; i++) a[i] = As[k][ty * 8 + i];
#pragma unroll
            for (int j = 0; j < 8; j++) bb[j] = Bs[k][tx * 8 + j];
#pragma unroll
            for (int i = 0; i < 8; i++)
#pragma unroll
                for (int j = 0; j < 8; j++)
                    acc[i][j] = fmaf(a[i], bb[j], acc[i][j]);
        }
        __syncthreads();
    }

    // bias add, write h, accumulate column stats
    float bv[8];
#pragma unroll
    for (int j = 0; j < 8; j++) bv[j] = bias[v * NO + n0 + tx * 8 + j];

    float csum[8], csq[8];
#pragma unroll
    for (int j = 0; j < 8; j++) { csum[j] = 0.f; csq[j] = 0.f; }

#pragma unroll
    for (int i = 0; i < 8; i++) {
        int m = m0 + ty * 8 + i;
        float* hrow = g_h + (size_t)m * (NV * NO) + v * NO + n0 + tx * 8;
        float hv[8];
#pragma unroll
        for (int j = 0; j < 8; j++) {
            hv[j]   = acc[i][j] + bv[j];
            csum[j] += hv[j];
            csq[j]  = fmaf(hv[j], hv[j], csq[j]);
        }
        *(float4*)(hrow)     = make_float4(hv[0], hv[1], hv[2], hv[3]);
        *(float4*)(hrow + 4) = make_float4(hv[4], hv[5], hv[6], hv[7]);
    }

    // reduce column sums across ty and atomically add to global stats
#pragma unroll
    for (int j = 0; j < 8; j++) red[ty][tx * 8 + j] = csum[j];
    __syncthreads();
    if (t < 128) {
        float s = 0.f;
#pragma unroll
        for (int r = 0; r < 16; r++) s += red[r][t];
        atomicAdd(&g_sum[v * NO + n0 + t], s);
    }
    __syncthreads();
#pragma unroll
    for (int j = 0; j < 8; j++) red[ty][tx * 8 + j] = csq[j];
    __syncthreads();
    if (t < 128) {
        float s = 0.f;
#pragma unroll
        for (int r = 0; r < 16; r++) s += red[r][t];
        atomicAdd(&g_sqs[v * NO + n0 + t], s);
    }
}

// ---------------------------------------------------------------------------
// Kernel 2: fold BN into affine:  s = gamma*rsqrt(var+eps), t = beta - mean*s
// ---------------------------------------------------------------------------
__global__ void compute_st(const float* __restrict__ gamma,
                           const float* __restrict__ beta) {
    int i = blockIdx.x * blockDim.x + threadIdx.x;   // exactly NV*NO threads
    float mean = g_sum[i] * (1.f / NB);
    float var  = g_sqs[i] * (1.f / NB) - mean * mean;
    float s    = gamma[i] * rsqrtf(var + EPS);
    g_s[i] = s;
    g_t[i] = beta[i] - mean * s;
}

// ---------------------------------------------------------------------------
// Kernel 3: c[u,o] = sum_v adj[u,v] * t[v,o]   (tiny: 64x256)
// ---------------------------------------------------------------------------
__global__ void compute_c(const float* __restrict__ adj) {
    int u = blockIdx.x;
    int o = threadIdx.x;
    float acc = 0.f;
#pragma unroll 8
    for (int vv = 0; vv < NV; vv++)
        acc = fmaf(adj[u * NV + vv], g_t[vv * NO + o], acc);
    g_c[u * NO + o] = acc;
}

// ---------------------------------------------------------------------------
// Kernel 4: out[b,u,o] = relu( sum_v adj[u,v] * s[v,o] * h[b,v,o] + c[u,o] )
// One block per batch index b. smem: scaled h[b] (64KB) + adj^T (16KB).
// Thread tile: 16 u x 4 o.
// ---------------------------------------------------------------------------
__global__ __launch_bounds__(256) void mix_relu(const float* __restrict__ adj,
                                                float* __restrict__ out) {
    extern __shared__ float sm[];
    float* hs   = sm;                 // [NV][NO] scaled h
    float* adjT = sm + NV * NO;       // [NV][NV]

    const int b = blockIdx.x;
    const int t = threadIdx.x;

    // stage s (.) h[b] into smem
    const float4* h4  = (const float4*)(g_h + (size_t)b * NV * NO);
    const float4* s4  = (const float4*)g_s;
    float4*       hs4 = (float4*)hs;
#pragma unroll
    for (int r = 0; r < 16; r++) {
        int idx = t + r * 256;        // 0..4095 float4s
        float4 h = h4[idx], s = s4[idx];
        hs4[idx] = make_float4(h.x * s.x, h.y * s.y, h.z * s.z, h.w * s.w);
    }
    // stage adj transposed: adjT[v][u] = adj[u][v]
#pragma unroll
    for (int r = 0; r < 16; r++) {
        int j  = t + r * 256;         // 0..4095
        int vv = j >> 6, u = j & 63;
        adjT[j] = adj[u * NV + vv];
    }
    __syncthreads();

    const int oq = t & 63;            // o = oq*4 .. oq*4+3
    const int ug = t >> 6;            // u = ug*16 .. ug*16+15
    float acc[16][4];
#pragma unroll
    for (int i = 0; i < 16; i++)
#pragma unroll
        for (int c = 0; c < 4; c++) acc[i][c] = 0.f;

    const float4* hsv = (const float4*)hs;
#pragma unroll 4
    for (int vv = 0; vv < NV; vv++) {
        float4 hv = hsv[vv * 64 + oq];
        const float4* arow = (const float4*)(adjT + vv * NV + ug * 16);
        float a[16];
#pragma unroll
        for (int q = 0; q < 4; q++) {
            float4 a4 = arow[q];
            a[q * 4 + 0] = a4.x; a[q * 4 + 1] = a4.y;
            a[q * 4 + 2] = a4.z; a[q * 4 + 3] = a4.w;
        }
#pragma unroll
        for (int i = 0; i < 16; i++) {
            acc[i][0] = fmaf(a[i], hv.x, acc[i][0]);
            acc[i][1] = fmaf(a[i], hv.y, acc[i][1]);
            acc[i][2] = fmaf(a[i], hv.z, acc[i][2]);
            acc[i][3] = fmaf(a[i], hv.w, acc[i][3]);
        }
    }

    float* ob = out + (size_t)b * NV * NO;
#pragma unroll
    for (int i = 0; i < 16; i++) {
        int u = ug * 16 + i;
        float4 cc = *(const float4*)(g_c + u * NO + oq * 4);
        float4 o4;
        o4.x = fmaxf(acc[i][0] + cc.x, 0.f);
        o4.y = fmaxf(acc[i][1] + cc.y, 0.f);
        o4.z = fmaxf(acc[i][2] + cc.z, 0.f);
        o4.w = fmaxf(acc[i][3] + cc.w, 0.f);
        *(float4*)(ob + u * NO + oq * 4) = o4;
    }
}

// ---------------------------------------------------------------------------
extern "C" void kernel_launch(void* const* d_in, const int* in_sizes, int n_in,
                              void* d_out, int out_size) {
    const float* feat  = (const float*)d_in[0];
    const float* adj   = (const float*)d_in[1];
    const float* W     = (const float*)d_in[2];
    const float* bias  = (const float*)d_in[3];
    const float* gamma = (const float*)d_in[4];
    const float* beta  = (const float*)d_in[5];
    float* out = (float*)d_out;

    const int smem_mix = (NV * NO + NV * NV) * sizeof(float);   // 80 KB
    cudaFuncSetAttribute(mix_relu, cudaFuncAttributeMaxDynamicSharedMemorySize,
                         smem_mix);

    zero_stats<<<64, 256>>>();
    dim3 gA(NO / 128, NB / 128, NV);
    gemm_stats<<<gA, 256>>>(feat, W, bias);
    compute_st<<<64, 256>>>(gamma, beta);
    compute_c<<<NV, NO>>>(adj);
    mix_relu<<<NB, 256, smem_mix>>>(adj, out);
}

// round 3
// speedup vs baseline: 1.3673x; 1.3673x over previous
#include <cuda_runtime.h>
#include <cuda_bf16.h>
#include <cstdint>

#define NB 1024
#define NV 64
#define NI 256
#define NO 256
constexpr float EPS = 1e-5f;

// ---------------------------------------------------------------------------
// Device scratch
// ---------------------------------------------------------------------------
__device__ float g_h[(size_t)NB * NV * NO];            // 64 MB: h = feat@W + b
__device__ __nv_bfloat16 g_Whi[(size_t)NV * NO * NI];  // 8 MB, layout [v][o][i]
__device__ __nv_bfloat16 g_Wlo[(size_t)NV * NO * NI];  // 8 MB
__device__ float g_s[NV * NO];
__device__ float g_t[NV * NO];

// ---------------------------------------------------------------------------
// Helpers (baseline PTX only — no sm_103a-specific features)
// ---------------------------------------------------------------------------
__device__ __forceinline__ uint32_t smem_u32(const void* p) {
    uint32_t a;
    asm("{ .reg .u64 t; cvta.to.shared.u64 t, %1; cvt.u32.u64 %0, t; }"
        : "=r"(a) : "l"(p));
    return a;
}
#define SWZ(off) ((uint32_t)(off) ^ ((((uint32_t)(off)) >> 3) & 0x70))

__device__ __forceinline__ void ldsm_x4(uint32_t* r, uint32_t addr) {
    asm volatile("ldmatrix.sync.aligned.m8n8.x4.shared.b16 {%0,%1,%2,%3}, [%4];"
                 : "=r"(r[0]), "=r"(r[1]), "=r"(r[2]), "=r"(r[3]) : "r"(addr));
}
__device__ __forceinline__ void ldsm_x2(uint32_t* r, uint32_t addr) {
    asm volatile("ldmatrix.sync.aligned.m8n8.x2.shared.b16 {%0,%1}, [%2];"
                 : "=r"(r[0]), "=r"(r[1]) : "r"(addr));
}
__device__ __forceinline__ void mma_bf16(float* d, const uint32_t* a,
                                         const uint32_t* b) {
    asm volatile(
        "mma.sync.aligned.m16n8k16.row.col.f32.bf16.bf16.f32 "
        "{%0,%1,%2,%3}, {%4,%5,%6,%7}, {%8,%9}, {%0,%1,%2,%3};"
        : "+f"(d[0]), "+f"(d[1]), "+f"(d[2]), "+f"(d[3])
        : "r"(a[0]), "r"(a[1]), "r"(a[2]), "r"(a[3]), "r"(b[0]), "r"(b[1]));
}

// ---------------------------------------------------------------------------
// Kernel A: split W into bf16 hi/lo, transposed to K-major [v][o][i]
// grid (NO/64, NV), block 256
// ---------------------------------------------------------------------------
__global__ __launch_bounds__(256) void convert_W(const float* __restrict__ W) {
    __shared__ float tile[256][65];
    const int v = blockIdx.y, o0 = blockIdx.x * 64;
    const int t = threadIdx.x;
    const float* src = W + (size_t)v * NI * NO + o0;
#pragma unroll 8
    for (int r = 0; r < 64; r++) {
        int idx = r * 256 + t;
        int i = idx >> 6, o = idx & 63;
        tile[i][o] = src[(size_t)i * NO + o];
    }
    __syncthreads();
    __nv_bfloat16* dh = g_Whi + ((size_t)v * NO + o0) * NI;
    __nv_bfloat16* dl = g_Wlo + ((size_t)v * NO + o0) * NI;
#pragma unroll 8
    for (int r = 0; r < 64; r++) {
        float x = tile[t][r];
        __nv_bfloat16 hi = __float2bfloat16(x);
        __nv_bfloat16 lo = __float2bfloat16(x - __bfloat162float(hi));
        dh[(size_t)r * NI + t] = hi;
        dl[(size_t)r * NI + t] = lo;
    }
}

// ---------------------------------------------------------------------------
// Kernel B: mma.sync split-bf16 GEMM  h[m,v,:] = feat[m,v,:] @ W[v] + bias[v]
// grid (NB/128, NO/128, NV), block 256 (8 warps), tile 128x128, K-chunks of 64
// warp tile 64x32: 4 m16-tiles x 4 n8-tiles; 3 mma terms (hh, hl, lh)
// ---------------------------------------------------------------------------
static constexpr int A_HI = 0;       // 128 x 64 bf16 = 16 KB
static constexpr int A_LO = 16384;
static constexpr int B_HI = 32768;
static constexpr int B_LO = 49152;
static constexpr int GEMM_DSMEM = 65536 + 1024;

__global__ __launch_bounds__(256, 2) void gemm_mma(const float* __restrict__ feat,
                                                   const float* __restrict__ bias) {
    extern __shared__ char dynraw[];
    uint32_t rawa = smem_u32(dynraw);
    char* smb = dynraw + (((rawa + 1023) & ~1023u) - rawa);
    const uint32_t aHi = smem_u32(smb);

    const int v  = blockIdx.z;
    const int m0 = blockIdx.x * 128;
    const int n0 = blockIdx.y * 128;
    const int t  = threadIdx.x;
    const int lane = t & 31;
    const int w = t >> 5;
    const int mw = (w >> 2) * 64;   // warp m offset within tile
    const int nw = (w & 3) * 32;    // warp n offset within tile

    float acc[4][4][4];
#pragma unroll
    for (int i = 0; i < 4; i++)
#pragma unroll
        for (int j = 0; j < 4; j++)
#pragma unroll
            for (int q = 0; q < 4; q++) acc[i][j][q] = 0.f;

    const __nv_bfloat16* Wh = g_Whi + ((size_t)v * NO + n0) * NI;
    const __nv_bfloat16* Wl = g_Wlo + ((size_t)v * NO + n0) * NI;

    for (int c = 0; c < 4; c++) {
        const int k0 = c * 64;
        if (c) __syncthreads();

        // ---- stage A: 128m x 64k fp32 -> bf16 hi/lo, swizzled
#pragma unroll
        for (int r = 0; r < 8; r++) {
            int idx = t + r * 256;            // 0..2047 float4s
            int m = idx >> 4, kq = idx & 15;
            float4 x = *(const float4*)(feat +
                        ((size_t)(m0 + m) * NV + v) * NI + k0 + kq * 4);
            __nv_bfloat16 h0 = __float2bfloat16(x.x);
            __nv_bfloat16 h1 = __float2bfloat16(x.y);
            __nv_bfloat16 h2 = __float2bfloat16(x.z);
            __nv_bfloat16 h3 = __float2bfloat16(x.w);
            __nv_bfloat16 l0 = __float2bfloat16(x.x - __bfloat162float(h0));
            __nv_bfloat16 l1 = __float2bfloat16(x.y - __bfloat162float(h1));
            __nv_bfloat16 l2 = __float2bfloat16(x.z - __bfloat162float(h2));
            __nv_bfloat16 l3 = __float2bfloat16(x.w - __bfloat162float(h3));
            uint32_t off = SWZ(m * 128 + kq * 8);
            __nv_bfloat162 hp0 = {h0, h1}, hp1 = {h2, h3};
            __nv_bfloat162 lp0 = {l0, l1}, lp1 = {l2, l3};
            *(uint2*)(smb + A_HI + off) =
                make_uint2(*(uint32_t*)&hp0, *(uint32_t*)&hp1);
            *(uint2*)(smb + A_LO + off) =
                make_uint2(*(uint32_t*)&lp0, *(uint32_t*)&lp1);
        }
        // ---- stage B: 128n x 64k bf16 hi+lo, swizzled 16B copies
#pragma unroll
        for (int r = 0; r < 4; r++) {
            int idx = t + r * 256;            // 0..1023
            int n = idx >> 3, kc = idx & 7;
            uint32_t off = SWZ(n * 128 + kc * 16);
            *(uint4*)(smb + B_HI + off) =
                *(const uint4*)(Wh + (size_t)n * NI + k0 + kc * 8);
            *(uint4*)(smb + B_LO + off) =
                *(const uint4*)(Wl + (size_t)n * NI + k0 + kc * 8);
        }
        __syncthreads();

        // ---- compute: 4 k-steps of 16
#pragma unroll
        for (int ks = 0; ks < 4; ks++) {
            uint32_t bh[4][2], bl[4][2];
            {
                int brow = nw + (lane & 7);
                int bk = ks * 16 + ((lane >> 3) & 1) * 8;
#pragma unroll
                for (int nt = 0; nt < 4; nt++) {
                    uint32_t addr =
                        aHi + B_HI + SWZ((brow + nt * 8) * 128 + bk * 2);
                    ldsm_x2(bh[nt], addr);
                    ldsm_x2(bl[nt], addr + (B_LO - B_HI));
                }
            }
            int arow = mw + (lane & 7) + ((lane >> 3) & 1) * 8;
            int ak = ks * 16 + ((lane >> 4) & 1) * 8;
#pragma unroll
            for (int mt = 0; mt < 4; mt++) {
                uint32_t ra[4], rl[4];
                uint32_t addr = aHi + SWZ((arow + mt * 16) * 128 + ak * 2);
                ldsm_x4(ra, addr);
                ldsm_x4(rl, addr + A_LO);
#pragma unroll
                for (int nt = 0; nt < 4; nt++) {
                    mma_bf16(acc[mt][nt], ra, bh[nt]);   // hi*hi
                    mma_bf16(acc[mt][nt], ra, bl[nt]);   // hi*lo
                    mma_bf16(acc[mt][nt], rl, bh[nt]);   // lo*hi
                }
            }
        }
    }

    // ---- epilogue: bias add + store h (fp32)
#pragma unroll
    for (int mt = 0; mt < 4; mt++) {
        int mlo = m0 + mw + mt * 16 + (lane >> 2);
#pragma unroll
        for (int nt = 0; nt < 4; nt++) {
            int n = n0 + nw + nt * 8 + (lane & 3) * 2;
            float2 bv = *(const float2*)(bias + v * NO + n);
            float2 o0, o1;
            o0.x = acc[mt][nt][0] + bv.x;
            o0.y = acc[mt][nt][1] + bv.y;
            o1.x = acc[mt][nt][2] + bv.x;
            o1.y = acc[mt][nt][3] + bv.y;
            *(float2*)(g_h + (size_t)mlo * (NV * NO) + v * NO + n) = o0;
            *(float2*)(g_h + (size_t)(mlo + 8) * (NV * NO) + v * NO + n) = o1;
        }
    }
}

// ---------------------------------------------------------------------------
// Kernel C: BN stats + fold:  s = gamma*rsqrt(var+eps), t = beta - mean*s
// ---------------------------------------------------------------------------
__global__ __launch_bounds__(256) void stats_st(const float* __restrict__ gamma,
                                                const float* __restrict__ beta) {
    const int col = blockIdx.x * 256 + threadIdx.x;  // 0..16383
    const float* p = g_h + col;
    float sum = 0.f, sq = 0.f;
#pragma unroll 16
    for (int b = 0; b < NB; b++) {
        float x = p[(size_t)b * (NV * NO)];
        sum += x;
        sq = fmaf(x, x, sq);
    }
    float mean = sum * (1.f / NB);
    float var  = sq * (1.f / NB) - mean * mean;
    float s    = gamma[col] * rsqrtf(var + EPS);
    g_s[col] = s;
    g_t[col] = fmaf(-mean, s, beta[col]);
}

// ---------------------------------------------------------------------------
// Kernel D: out[b,u,o] = relu( sum_v adj[u,v] * (s[v,o]*h[b,v,o] + t[v,o]) )
// ---------------------------------------------------------------------------
__global__ __launch_bounds__(256) void mix_relu(const float* __restrict__ adj,
                                                float* __restrict__ out) {
    extern __shared__ float sm[];
    float* hs   = sm;             // [NV][NO] = s*h + t
    float* adjT = sm + NV * NO;   // [NV][NV]

    const int b = blockIdx.x;
    const int t = threadIdx.x;

    const float4* h4  = (const float4*)(g_h + (size_t)b * NV * NO);
    const float4* s4  = (const float4*)g_s;
    const float4* t4  = (const float4*)g_t;
    float4*       hs4 = (float4*)hs;
#pragma unroll
    for (int r = 0; r < 16; r++) {
        int idx = t + r * 256;
        float4 h = h4[idx], s = s4[idx], tt = t4[idx];
        hs4[idx] = make_float4(fmaf(h.x, s.x, tt.x), fmaf(h.y, s.y, tt.y),
                               fmaf(h.z, s.z, tt.z), fmaf(h.w, s.w, tt.w));
    }
#pragma unroll
    for (int r = 0; r < 16; r++) {
        int j  = t + r * 256;
        int vv = j >> 6, u = j & 63;
        adjT[j] = adj[u * NV + vv];
    }
    __syncthreads();

    const int oq = t & 63;
    const int ug = t >> 6;
    float acc[16][4];
#pragma unroll
    for (int i = 0; i < 16; i++)
#pragma unroll
        for (int c = 0; c < 4; c++) acc[i][c] = 0.f;

    const float4* hsv = (const float4*)hs;
#pragma unroll 4
    for (int vv = 0; vv < NV; vv++) {
        float4 hv = hsv[vv * 64 + oq];
        const float4* arow = (const float4*)(adjT + vv * NV + ug * 16);
        float a[16];
#pragma unroll
        for (int q = 0; q < 4; q++) {
            float4 a4 = arow[q];
            a[q * 4 + 0] = a4.x; a[q * 4 + 1] = a4.y;
            a[q * 4 + 2] = a4.z; a[q * 4 + 3] = a4.w;
        }
#pragma unroll
        for (int i = 0; i < 16; i++) {
            acc[i][0] = fmaf(a[i], hv.x, acc[i][0]);
            acc[i][1] = fmaf(a[i], hv.y, acc[i][1]);
            acc[i][2] = fmaf(a[i], hv.z, acc[i][2]);
            acc[i][3] = fmaf(a[i], hv.w, acc[i][3]);
        }
    }

    float* ob = out + (size_t)b * NV * NO;
#pragma unroll
    for (int i = 0; i < 16; i++) {
        int u = ug * 16 + i;
        float4 o4;
        o4.x = fmaxf(acc[i][0], 0.f);
        o4.y = fmaxf(acc[i][1], 0.f);
        o4.z = fmaxf(acc[i][2], 0.f);
        o4.w = fmaxf(acc[i][3], 0.f);
        *(float4*)(ob + u * NO + oq * 4) = o4;
    }
}

// ---------------------------------------------------------------------------
extern "C" void kernel_launch(void* const* d_in, const int* in_sizes, int n_in,
                              void* d_out, int out_size) {
    const float* feat  = (const float*)d_in[0];
    const float* adj   = (const float*)d_in[1];
    const float* W     = (const float*)d_in[2];
    const float* bias  = (const float*)d_in[3];
    const float* gamma = (const float*)d_in[4];
    const float* beta  = (const float*)d_in[5];
    float* out = (float*)d_out;

    cudaFuncSetAttribute(gemm_mma, cudaFuncAttributeMaxDynamicSharedMemorySize,
                         GEMM_DSMEM);
    const int smem_mix = (NV * NO + NV * NV) * sizeof(float);  // 80 KB
    cudaFuncSetAttribute(mix_relu, cudaFuncAttributeMaxDynamicSharedMemorySize,
                         smem_mix);

    convert_W<<<dim3(NO / 64, NV), 256>>>(W);
    gemm_mma<<<dim3(NB / 128, NO / 128, NV), 256, GEMM_DSMEM>>>(feat, bias);
    stats_st<<<64, 256>>>(gamma, beta);
    mix_relu<<<NB, 256, smem_mix>>>(adj, out);
}